// round 13
// baseline (speedup 1.0000x reference)
#include <cuda_runtime.h>

#define NEGV (-1e30f)

__device__ __forceinline__ float4 fmax4(float4 a, float4 b) {
    a.x = fmaxf(a.x, b.x);
    a.y = fmaxf(a.y, b.y);
    a.z = fmaxf(a.z, b.z);
    a.w = fmaxf(a.w, b.w);
    return a;
}

// One block (64 threads = 2 warps) per (token, side):
//   warp 0: d[  0:128)
//   warp 1: d[128:256)
// Trade occupancy for MLP: launch_bounds(64, 26) gives ptxas a ~39-reg
// budget (52 warps/SM) so the compiler-unrolled 8-chunk loop can keep ~7
// gather LDG.128 in flight per warp (vs 4 at the 32-reg/64-warp point).
// Dynamic-bound loop + pragma unroll 8 = unpredicated 8-chunks + remainder.
// Lane p holds paths[token][p] (P == 32); index broadcast is a shfl on
// register state only, so unrolled loads are mutually independent.
__global__ __launch_bounds__(64, 26) void path_max_kernel(
    const float* __restrict__ inputs,   // [B,L,D] f32, D=256
    const int*   __restrict__ lpaths,   // [B,L,P]
    const int*   __restrict__ rpaths,   // [B,L,P]
    const int*   __restrict__ llens,    // [B,L]
    const int*   __restrict__ rlens,    // [B,L]
    const int*   __restrict__ slens,    // [B]
    float*       __restrict__ out)      // [B,L,2D]
{
    constexpr int L = 512, P = 32;

    const int token = blockIdx.x >> 1;
    const int side  = blockIdx.x & 1;    // 0 = left, 1 = right
    const int half  = threadIdx.x >> 5;  // 0 = d[0:128), 1 = d[128:256)
    const int lane  = threadIdx.x & 31;
    const int b     = token >> 9;        // token / L
    const int l     = token & (L - 1);   // token % L

    // Token row has 512 floats = 128 float4; this warp owns 32 of them.
    float4* o4 = reinterpret_cast<float4*>(out)
               + (size_t)token * 128 + side * 64 + half * 32 + lane;

    if (l >= __ldg(&slens[b])) {
        *o4 = make_float4(0.f, 0.f, 0.f, 0.f);
        return;
    }

    const int* __restrict__ paths = side ? rpaths : lpaths;
    const int len = side ? __ldg(&rlens[token]) : __ldg(&llens[token]);
    const int my  = __ldg(&paths[(size_t)token * P + lane]);

    // Each row of inputs[b] is 64 float4; this warp reads float4 column
    // (half*32 + lane) of each gathered row -> coalesced 512B per LDG.128.
    const float4* __restrict__ base =
        reinterpret_cast<const float4*>(inputs)
        + (size_t)b * L * 64 + half * 32 + lane;

    float4 m0 = make_float4(NEGV, NEGV, NEGV, NEGV);
    float4 m1 = m0;

    int idx = __shfl_sync(0xffffffffu, my, 0);
    #pragma unroll 8
    for (int p = 0; p < len; ++p) {
        const float4 v = __ldg(base + (size_t)idx * 64);
        idx = __shfl_sync(0xffffffffu, my, (p + 1) & 31);  // independent of v
        if (p & 1) m1 = fmax4(m1, v);
        else       m0 = fmax4(m0, v);
    }

    *o4 = fmax4(m0, m1);
}

extern "C" void kernel_launch(void* const* d_in, const int* in_sizes, int n_in,
                              void* d_out, int out_size) {
    const float* inputs = (const float*)d_in[0];
    const int*   lpaths = (const int*)d_in[1];
    const int*   rpaths = (const int*)d_in[2];
    const int*   llens  = (const int*)d_in[3];
    const int*   rlens  = (const int*)d_in[4];
    const int*   slens  = (const int*)d_in[5];

    const int B = in_sizes[5];          // sent_lens has B elements
    const int blocks = B * 512 * 2;     // one block per (token, side)

    path_max_kernel<<<blocks, 64>>>(inputs, lpaths, rpaths,
                                    llens, rlens, slens,
                                    (float*)d_out);
}

// round 14
// speedup vs baseline: 1.0216x; 1.0216x over previous
#include <cuda_runtime.h>

#define NEGV (-1e30f)

__device__ __forceinline__ float4 fmax4(float4 a, float4 b) {
    a.x = fmaxf(a.x, b.x);
    a.y = fmaxf(a.y, b.y);
    a.z = fmaxf(a.z, b.z);
    a.w = fmaxf(a.w, b.w);
    return a;
}

// One block (64 threads = 2 warps) per (token, side):
//   warp 0: d[  0:128)
//   warp 1: d[128:256)
// Registers-for-MLP experiment: __launch_bounds__(64, 24) gives ptxas a
// 42-reg budget (allocates 40, vs the 32-reg clamp of (64,26+)), so the
// unroll-8 loop can hold ~6-8 independent gather LDG.128 in flight per
// warp at 48 warps/SM theoretical (24 blocks x 2 warps).
// Lane p holds paths[token][p] (P == 32); index broadcast is a shfl on
// register state only, so unrolled loads are mutually independent.
__global__ __launch_bounds__(64, 24) void path_max_kernel(
    const float* __restrict__ inputs,   // [B,L,D] f32, D=256
    const int*   __restrict__ lpaths,   // [B,L,P]
    const int*   __restrict__ rpaths,   // [B,L,P]
    const int*   __restrict__ llens,    // [B,L]
    const int*   __restrict__ rlens,    // [B,L]
    const int*   __restrict__ slens,    // [B]
    float*       __restrict__ out)      // [B,L,2D]
{
    constexpr int L = 512, P = 32;

    const int token = blockIdx.x >> 1;
    const int side  = blockIdx.x & 1;    // 0 = left, 1 = right
    const int half  = threadIdx.x >> 5;  // 0 = d[0:128), 1 = d[128:256)
    const int lane  = threadIdx.x & 31;
    const int b     = token >> 9;        // token / L
    const int l     = token & (L - 1);   // token % L

    // Token row has 512 floats = 128 float4; this warp owns 32 of them.
    float4* o4 = reinterpret_cast<float4*>(out)
               + (size_t)token * 128 + side * 64 + half * 32 + lane;

    if (l >= __ldg(&slens[b])) {
        *o4 = make_float4(0.f, 0.f, 0.f, 0.f);
        return;
    }

    const int* __restrict__ paths = side ? rpaths : lpaths;
    const int len = side ? __ldg(&rlens[token]) : __ldg(&llens[token]);
    const int my  = __ldg(&paths[(size_t)token * P + lane]);

    // Each row of inputs[b] is 64 float4; this warp reads float4 column
    // (half*32 + lane) of each gathered row -> coalesced 512B per LDG.128.
    const float4* __restrict__ base =
        reinterpret_cast<const float4*>(inputs)
        + (size_t)b * L * 64 + half * 32 + lane;

    float4 m0 = make_float4(NEGV, NEGV, NEGV, NEGV);
    float4 m1 = m0;

    int idx = __shfl_sync(0xffffffffu, my, 0);
    #pragma unroll 8
    for (int p = 0; p < len; ++p) {
        const float4 v = __ldg(base + (size_t)idx * 64);
        idx = __shfl_sync(0xffffffffu, my, (p + 1) & 31);  // independent of v
        if (p & 1) m1 = fmax4(m1, v);
        else       m0 = fmax4(m0, v);
    }

    *o4 = fmax4(m0, m1);
}

extern "C" void kernel_launch(void* const* d_in, const int* in_sizes, int n_in,
                              void* d_out, int out_size) {
    const float* inputs = (const float*)d_in[0];
    const int*   lpaths = (const int*)d_in[1];
    const int*   rpaths = (const int*)d_in[2];
    const int*   llens  = (const int*)d_in[3];
    const int*   rlens  = (const int*)d_in[4];
    const int*   slens  = (const int*)d_in[5];

    const int B = in_sizes[5];          // sent_lens has B elements
    const int blocks = B * 512 * 2;     // one block per (token, side)

    path_max_kernel<<<blocks, 64>>>(inputs, lpaths, rpaths,
                                    llens, rlens, slens,
                                    (float*)d_out);
}